// round 4
// baseline (speedup 1.0000x reference)
#include <cuda_runtime.h>
#include <cuda_fp16.h>
#include <stdint.h>

#define NU 100000
#define NB 50000
#define NN 150000
#define D  64
#define NE 2400000

#define SCAN_BLK 1024
#define NBLK ((NN + SCAN_BLK - 1) / SCAN_BLK)   // 147

// ---------------- scratch (device globals: allocation-free) ----------------
__device__ __half g_h16A[NN * D];    // fp16: emb0 copy, then e2
__device__ __half g_h16B[NN * D];    // fp16: e1
__device__ int    g_deg[NN];
__device__ float  g_dinv[NN];
__device__ int    g_off[NN + 1];
__device__ int    g_cur[NN];
__device__ int2   g_csr[NE];         // (frm, norm bits) interleaved
__device__ int    g_partial[NBLK];

// ---------------- kernels ----------------

__global__ void k_zero_deg() {
    int i = blockIdx.x * blockDim.x + threadIdx.x;
    if (i < NN) g_deg[i] = 0;
}

// emb0 = embedding + concat(user_proj, book_proj); writes out0 (fp32) and fp16 copy
__global__ void k_emb0(const float* __restrict__ emb,
                       const float* __restrict__ uf,
                       const float* __restrict__ bnf,
                       const float* __restrict__ bgf,
                       const float* __restrict__ Wu, const float* __restrict__ bu,
                       const float* __restrict__ Wn, const float* __restrict__ bn,
                       const float* __restrict__ Wg, const float* __restrict__ bg,
                       float* __restrict__ out_emb0) {
    int node = blockIdx.x * 4 + (threadIdx.x >> 6);
    int d    = threadIdx.x & 63;
    if (node >= NN) return;
    float v = emb[node * D + d];
    if (node < NU) {
        const float* f = uf + node * 16;
        float s = bu[d];
#pragma unroll
        for (int k = 0; k < 16; k++) s += f[k] * Wu[k * D + d];
        v += s;
    } else {
        int b = node - NU;
        float s = bn[d] + bg[d];
        const float* fn = bnf + b * 8;
#pragma unroll
        for (int k = 0; k < 8; k++) s += fn[k] * Wn[k * D + d];
        const float* fg = bgf + b * 32;
#pragma unroll
        for (int k = 0; k < 32; k++) s += fg[k] * Wg[k * D + d];
        v += s;
    }
    int o = node * D + d;
    out_emb0[o] = v;
    g_h16A[o]   = __float2half_rn(v);
}

__global__ void k_degree(const int* __restrict__ to) {
    int e = blockIdx.x * blockDim.x + threadIdx.x;
    if (e < NE) atomicAdd(&g_deg[to[e]], 1);
}

// phase 1: per-block reduce of deg -> g_partial[b]; also compute dinv
__global__ void k_scan1() {
    __shared__ int s[SCAN_BLK / 32];
    int t = threadIdx.x;
    int i = blockIdx.x * SCAN_BLK + t;
    int v = (i < NN) ? g_deg[i] : 0;
    if (i < NN) g_dinv[i] = (v > 0) ? rsqrtf((float)v) : 0.0f;
    int w = v;
#pragma unroll
    for (int o = 16; o > 0; o >>= 1) w += __shfl_down_sync(0xffffffffu, w, o);
    if ((t & 31) == 0) s[t >> 5] = w;
    __syncthreads();
    if (t < SCAN_BLK / 32) {
        int x = s[t];
#pragma unroll
        for (int o = 16; o > 0; o >>= 1) x += __shfl_down_sync(0xffffffffu, x, o);
        if (t == 0) g_partial[blockIdx.x] = x;
    }
}

// phase 2: single block exclusive scan of NBLK partials (147 <= 256)
__global__ void k_scan2() {
    __shared__ int s[256];
    int t = threadIdx.x;
    int v = (t < NBLK) ? g_partial[t] : 0;
    s[t] = v;
    __syncthreads();
#pragma unroll
    for (int o = 1; o < 256; o <<= 1) {
        int y = (t >= o) ? s[t - o] : 0;
        __syncthreads();
        s[t] += y;
        __syncthreads();
    }
    if (t < NBLK) g_partial[t] = s[t] - v;
}

// phase 3: per-block exclusive scan + block offset -> g_off, g_cur
__global__ void k_scan3() {
    __shared__ int s[SCAN_BLK];
    int t = threadIdx.x;
    int i = blockIdx.x * SCAN_BLK + t;
    int v = (i < NN) ? g_deg[i] : 0;
    s[t] = v;
    __syncthreads();
#pragma unroll
    for (int o = 1; o < SCAN_BLK; o <<= 1) {
        int y = (t >= o) ? s[t - o] : 0;
        __syncthreads();
        s[t] += y;
        __syncthreads();
    }
    if (i < NN) {
        int ex = g_partial[blockIdx.x] + s[t] - v;
        g_off[i] = ex;
        g_cur[i] = ex;
    }
    if (i == NN - 1) g_off[NN] = NE;
}

__global__ void k_scatter(const int* __restrict__ frm, const int* __restrict__ to) {
    int e = blockIdx.x * blockDim.x + threadIdx.x;
    if (e < NE) {
        int tt = to[e];
        int ff = frm[e];
        int p  = atomicAdd(&g_cur[tt], 1);
        float w = g_dinv[ff] * g_dinv[tt];
        g_csr[p] = make_int2(ff, __float_as_int(w));
    }
}

// shared gather core: 8 lanes/node, lane loads uint4 = 8 halves, fp32 accum
__device__ __forceinline__ void gather_node(const uint4* __restrict__ src16,
                                            int gid, int lane,
                                            float4& a0, float4& a1) {
    int s = g_off[gid];
    int e = g_off[gid + 1];
    for (int base = s; base < e; base += 8) {
        int idx = base + lane;
        int2 fw = (idx < e) ? g_csr[idx] : make_int2(0, 0);
        int m = min(8, e - base);
#pragma unroll 8
        for (int j = 0; j < m; j++) {
            int   fj = __shfl_sync(0xffffffffu, fw.x, j, 8);
            float wj = __int_as_float(__shfl_sync(0xffffffffu, fw.y, j, 8));
            uint4 x  = src16[fj * 8 + lane];
            float2 f0 = __half22float2(*(const __half2*)&x.x);
            float2 f1 = __half22float2(*(const __half2*)&x.y);
            float2 f2 = __half22float2(*(const __half2*)&x.z);
            float2 f3 = __half22float2(*(const __half2*)&x.w);
            a0.x += wj * f0.x;  a0.y += wj * f0.y;
            a0.z += wj * f1.x;  a0.w += wj * f1.y;
            a1.x += wj * f2.x;  a1.y += wj * f2.y;
            a1.z += wj * f3.x;  a1.w += wj * f3.y;
        }
    }
}

// mid layer: pure gather -> fp16 store (no fp32 acc traffic)
__global__ void k_prop_mid(const __half* __restrict__ src,
                           __half* __restrict__ dst) {
    int gid  = (blockIdx.x * blockDim.x + threadIdx.x) >> 3;
    int lane = threadIdx.x & 7;
    if (gid >= NN) return;
    float4 a0 = make_float4(0.f, 0.f, 0.f, 0.f);
    float4 a1 = make_float4(0.f, 0.f, 0.f, 0.f);
    gather_node((const uint4*)src, gid, lane, a0, a1);
    __half2 h0 = __floats2half2_rn(a0.x, a0.y);
    __half2 h1 = __floats2half2_rn(a0.z, a0.w);
    __half2 h2 = __floats2half2_rn(a1.x, a1.y);
    __half2 h3 = __floats2half2_rn(a1.z, a1.w);
    uint4 hx;
    hx.x = *(const unsigned*)&h0;
    hx.y = *(const unsigned*)&h1;
    hx.z = *(const unsigned*)&h2;
    hx.w = *(const unsigned*)&h3;
    ((uint4*)dst)[gid * 8 + lane] = hx;
}

// final layer: e3 = gather(e2); acc = (emb0 + e1 + e2 + e3) / 4, single write
__global__ void k_prop_final(const __half* __restrict__ e2src,   // = g_h16A
                             const __half* __restrict__ e1src,   // = g_h16B
                             const float4* __restrict__ emb0_4,
                             float4* __restrict__ acc4) {
    int gid  = (blockIdx.x * blockDim.x + threadIdx.x) >> 3;
    int lane = threadIdx.x & 7;
    if (gid >= NN) return;
    float4 a0 = make_float4(0.f, 0.f, 0.f, 0.f);
    float4 a1 = make_float4(0.f, 0.f, 0.f, 0.f);
    gather_node((const uint4*)e2src, gid, lane, a0, a1);   // a = e3

    // own-row reads: emb0 (fp32), e1, e2 (fp16)
    int ho = gid * 8 + lane;                 // uint4 index into fp16 rows
    uint4 x1 = ((const uint4*)e1src)[ho];
    uint4 x2 = ((const uint4*)e2src)[ho];
    float2 p0 = __half22float2(*(const __half2*)&x1.x);
    float2 p1 = __half22float2(*(const __half2*)&x1.y);
    float2 p2 = __half22float2(*(const __half2*)&x1.z);
    float2 p3 = __half22float2(*(const __half2*)&x1.w);
    float2 q0 = __half22float2(*(const __half2*)&x2.x);
    float2 q1 = __half22float2(*(const __half2*)&x2.y);
    float2 q2 = __half22float2(*(const __half2*)&x2.z);
    float2 q3 = __half22float2(*(const __half2*)&x2.w);

    int o = gid * 16 + lane * 2;             // float4 index into fp32 rows
    float4 z0 = emb0_4[o];
    float4 z1 = emb0_4[o + 1];

    float4 r0, r1;
    r0.x = (z0.x + p0.x + q0.x + a0.x) * 0.25f;
    r0.y = (z0.y + p0.y + q0.y + a0.y) * 0.25f;
    r0.z = (z0.z + p1.x + q1.x + a0.z) * 0.25f;
    r0.w = (z0.w + p1.y + q1.y + a0.w) * 0.25f;
    r1.x = (z1.x + p2.x + q2.x + a1.x) * 0.25f;
    r1.y = (z1.y + p2.y + q2.y + a1.y) * 0.25f;
    r1.z = (z1.z + p3.x + q3.x + a1.z) * 0.25f;
    r1.w = (z1.w + p3.y + q3.y + a1.w) * 0.25f;
    acc4[o]     = r0;
    acc4[o + 1] = r1;
}

// ---------------- launch ----------------
extern "C" void kernel_launch(void* const* d_in, const int* in_sizes, int n_in,
                              void* d_out, int out_size) {
    const int*   ei   = (const int*)d_in[0];
    const int*   frm  = ei;
    const int*   to   = ei + NE;
    const float* emb  = (const float*)d_in[1];
    const float* uf   = (const float*)d_in[2];
    const float* bnf  = (const float*)d_in[3];
    const float* bgf  = (const float*)d_in[4];
    const float* Wu   = (const float*)d_in[5];
    const float* bu   = (const float*)d_in[6];
    const float* Wn   = (const float*)d_in[7];
    const float* bn   = (const float*)d_in[8];
    const float* Wg   = (const float*)d_in[9];
    const float* bg   = (const float*)d_in[10];

    float* out  = (float*)d_out;
    float* out0 = out;              // emb0 (fp32, exact)
    float* acc  = out + NN * D;     // final output, written once

    __half* hA;
    __half* hB;
    cudaGetSymbolAddress((void**)&hA, g_h16A);
    cudaGetSymbolAddress((void**)&hB, g_h16B);

    k_zero_deg<<<(NN + 255) / 256, 256>>>();
    k_emb0<<<(NN + 3) / 4, 256>>>(emb, uf, bnf, bgf, Wu, bu, Wn, bn, Wg, bg, out0);
    k_degree<<<(NE + 255) / 256, 256>>>(to);
    k_scan1<<<NBLK, SCAN_BLK>>>();
    k_scan2<<<1, 256>>>();
    k_scan3<<<NBLK, SCAN_BLK>>>();
    k_scatter<<<(NE + 255) / 256, 256>>>(frm, to);

    int prop_threads = NN * 8;
    int prop_blocks  = (prop_threads + 255) / 256;
    k_prop_mid<<<prop_blocks, 256>>>(hA, hB);                 // e1 = prop(emb0): A -> B
    k_prop_mid<<<prop_blocks, 256>>>(hB, hA);                 // e2 = prop(e1):   B -> A
    k_prop_final<<<prop_blocks, 256>>>(hA, hB,
                                       (const float4*)out0, (float4*)acc);  // e3 + combine
}

// round 5
// speedup vs baseline: 1.8897x; 1.8897x over previous
#include <cuda_runtime.h>
#include <cuda_fp16.h>
#include <stdint.h>

#define NU 100000
#define NB 50000
#define NN 150000
#define D  64
#define NE 2400000

#define SCAN_BLK 1024
#define NBLK ((NN + SCAN_BLK - 1) / SCAN_BLK)   // 147

// ---------------- scratch (device globals: allocation-free) ----------------
__device__ __half g_h16A[NN * D];    // fp16: emb0 copy, then e2
__device__ __half g_h16B[NN * D];    // fp16: e1
__device__ int    g_deg[NN];
__device__ float  g_dinv[NN];
__device__ int    g_off[NN + 1];
__device__ int    g_cur[NN];
__device__ int2   g_csr[NE];         // (frm, norm bits) interleaved
__device__ int    g_partial[NBLK];

// ---------------- kernels ----------------

__global__ void k_zero_deg() {
    int i = blockIdx.x * blockDim.x + threadIdx.x;
    if (i < NN) g_deg[i] = 0;
}

// emb0 = embedding + concat(user_proj, book_proj); writes out0 (fp32) and fp16 copy
__global__ void k_emb0(const float* __restrict__ emb,
                       const float* __restrict__ uf,
                       const float* __restrict__ bnf,
                       const float* __restrict__ bgf,
                       const float* __restrict__ Wu, const float* __restrict__ bu,
                       const float* __restrict__ Wn, const float* __restrict__ bn,
                       const float* __restrict__ Wg, const float* __restrict__ bg,
                       float* __restrict__ out_emb0) {
    int node = blockIdx.x * 4 + (threadIdx.x >> 6);
    int d    = threadIdx.x & 63;
    if (node >= NN) return;
    float v = emb[node * D + d];
    if (node < NU) {
        const float* f = uf + node * 16;
        float s = bu[d];
#pragma unroll
        for (int k = 0; k < 16; k++) s += f[k] * Wu[k * D + d];
        v += s;
    } else {
        int b = node - NU;
        float s = bn[d] + bg[d];
        const float* fn = bnf + b * 8;
#pragma unroll
        for (int k = 0; k < 8; k++) s += fn[k] * Wn[k * D + d];
        const float* fg = bgf + b * 32;
#pragma unroll
        for (int k = 0; k < 32; k++) s += fg[k] * Wg[k * D + d];
        v += s;
    }
    int o = node * D + d;
    out_emb0[o] = v;
    g_h16A[o]   = __float2half_rn(v);
}

__global__ void k_degree(const int* __restrict__ to) {
    int e = blockIdx.x * blockDim.x + threadIdx.x;
    if (e < NE) atomicAdd(&g_deg[to[e]], 1);
}

// phase 1: per-block reduce of deg -> g_partial[b]; also compute dinv
__global__ void k_scan1() {
    __shared__ int s[SCAN_BLK / 32];
    int t = threadIdx.x;
    int i = blockIdx.x * SCAN_BLK + t;
    int v = (i < NN) ? g_deg[i] : 0;
    if (i < NN) g_dinv[i] = (v > 0) ? rsqrtf((float)v) : 0.0f;
    int w = v;
#pragma unroll
    for (int o = 16; o > 0; o >>= 1) w += __shfl_down_sync(0xffffffffu, w, o);
    if ((t & 31) == 0) s[t >> 5] = w;
    __syncthreads();
    if (t < SCAN_BLK / 32) {
        int x = s[t];
#pragma unroll
        for (int o = 16; o > 0; o >>= 1) x += __shfl_down_sync(0xffffffffu, x, o);
        if (t == 0) g_partial[blockIdx.x] = x;
    }
}

// phase 2: single block exclusive scan of NBLK partials (147 <= 256)
__global__ void k_scan2() {
    __shared__ int s[256];
    int t = threadIdx.x;
    int v = (t < NBLK) ? g_partial[t] : 0;
    s[t] = v;
    __syncthreads();
#pragma unroll
    for (int o = 1; o < 256; o <<= 1) {
        int y = (t >= o) ? s[t - o] : 0;
        __syncthreads();
        s[t] += y;
        __syncthreads();
    }
    if (t < NBLK) g_partial[t] = s[t] - v;
}

// phase 3: per-block exclusive scan + block offset -> g_off, g_cur
__global__ void k_scan3() {
    __shared__ int s[SCAN_BLK];
    int t = threadIdx.x;
    int i = blockIdx.x * SCAN_BLK + t;
    int v = (i < NN) ? g_deg[i] : 0;
    s[t] = v;
    __syncthreads();
#pragma unroll
    for (int o = 1; o < SCAN_BLK; o <<= 1) {
        int y = (t >= o) ? s[t - o] : 0;
        __syncthreads();
        s[t] += y;
        __syncthreads();
    }
    if (i < NN) {
        int ex = g_partial[blockIdx.x] + s[t] - v;
        g_off[i] = ex;
        g_cur[i] = ex;
    }
    if (i == NN - 1) g_off[NN] = NE;
}

__global__ void k_scatter(const int* __restrict__ frm, const int* __restrict__ to) {
    int e = blockIdx.x * blockDim.x + threadIdx.x;
    if (e < NE) {
        int tt = to[e];
        int ff = frm[e];
        int p  = atomicAdd(&g_cur[tt], 1);
        float w = g_dinv[ff] * g_dinv[tt];
        g_csr[p] = make_int2(ff, __float_as_int(w));
    }
}

// shared gather core: 8 lanes/node, lane loads uint4 = 8 halves, fp32 accum
// NOTE: inner unroll kept at 4 — unroll 8 caused register spill (R4 regression).
__device__ __forceinline__ void gather_node(const uint4* __restrict__ src16,
                                            int gid, int lane,
                                            float4& a0, float4& a1) {
    int s = g_off[gid];
    int e = g_off[gid + 1];
    for (int base = s; base < e; base += 8) {
        int idx = base + lane;
        int2 fw = (idx < e) ? g_csr[idx] : make_int2(0, 0);
        int m = min(8, e - base);
#pragma unroll 4
        for (int j = 0; j < m; j++) {
            int   fj = __shfl_sync(0xffffffffu, fw.x, j, 8);
            float wj = __int_as_float(__shfl_sync(0xffffffffu, fw.y, j, 8));
            uint4 x  = src16[fj * 8 + lane];
            float2 f0 = __half22float2(*(const __half2*)&x.x);
            float2 f1 = __half22float2(*(const __half2*)&x.y);
            float2 f2 = __half22float2(*(const __half2*)&x.z);
            float2 f3 = __half22float2(*(const __half2*)&x.w);
            a0.x += wj * f0.x;  a0.y += wj * f0.y;
            a0.z += wj * f1.x;  a0.w += wj * f1.y;
            a1.x += wj * f2.x;  a1.y += wj * f2.y;
            a1.z += wj * f3.x;  a1.w += wj * f3.y;
        }
    }
}

// mid layer: pure gather -> fp16 store (no fp32 acc traffic)
__global__ void __launch_bounds__(256) k_prop_mid(const __half* __restrict__ src,
                                                  __half* __restrict__ dst) {
    int gid  = (blockIdx.x * blockDim.x + threadIdx.x) >> 3;
    int lane = threadIdx.x & 7;
    if (gid >= NN) return;
    float4 a0 = make_float4(0.f, 0.f, 0.f, 0.f);
    float4 a1 = make_float4(0.f, 0.f, 0.f, 0.f);
    gather_node((const uint4*)src, gid, lane, a0, a1);
    __half2 h0 = __floats2half2_rn(a0.x, a0.y);
    __half2 h1 = __floats2half2_rn(a0.z, a0.w);
    __half2 h2 = __floats2half2_rn(a1.x, a1.y);
    __half2 h3 = __floats2half2_rn(a1.z, a1.w);
    uint4 hx;
    hx.x = *(const unsigned*)&h0;
    hx.y = *(const unsigned*)&h1;
    hx.z = *(const unsigned*)&h2;
    hx.w = *(const unsigned*)&h3;
    ((uint4*)dst)[gid * 8 + lane] = hx;
}

// final layer: e3 = gather(e2); acc = (emb0 + e1 + e2 + e3) / 4, single write
__global__ void __launch_bounds__(256) k_prop_final(const __half* __restrict__ e2src,
                                                    const __half* __restrict__ e1src,
                                                    const float4* __restrict__ emb0_4,
                                                    float4* __restrict__ acc4) {
    int gid  = (blockIdx.x * blockDim.x + threadIdx.x) >> 3;
    int lane = threadIdx.x & 7;
    if (gid >= NN) return;
    float4 a0 = make_float4(0.f, 0.f, 0.f, 0.f);
    float4 a1 = make_float4(0.f, 0.f, 0.f, 0.f);
    gather_node((const uint4*)e2src, gid, lane, a0, a1);   // a = e3

    // own-row reads: emb0 (fp32), e1, e2 (fp16)
    int ho = gid * 8 + lane;                 // uint4 index into fp16 rows
    uint4 x1 = ((const uint4*)e1src)[ho];
    uint4 x2 = ((const uint4*)e2src)[ho];
    float2 p0 = __half22float2(*(const __half2*)&x1.x);
    float2 p1 = __half22float2(*(const __half2*)&x1.y);
    float2 p2 = __half22float2(*(const __half2*)&x1.z);
    float2 p3 = __half22float2(*(const __half2*)&x1.w);
    float2 q0 = __half22float2(*(const __half2*)&x2.x);
    float2 q1 = __half22float2(*(const __half2*)&x2.y);
    float2 q2 = __half22float2(*(const __half2*)&x2.z);
    float2 q3 = __half22float2(*(const __half2*)&x2.w);

    int o = gid * 16 + lane * 2;             // float4 index into fp32 rows
    float4 z0 = emb0_4[o];
    float4 z1 = emb0_4[o + 1];

    float4 r0, r1;
    r0.x = (z0.x + p0.x + q0.x + a0.x) * 0.25f;
    r0.y = (z0.y + p0.y + q0.y + a0.y) * 0.25f;
    r0.z = (z0.z + p1.x + q1.x + a0.z) * 0.25f;
    r0.w = (z0.w + p1.y + q1.y + a0.w) * 0.25f;
    r1.x = (z1.x + p2.x + q2.x + a1.x) * 0.25f;
    r1.y = (z1.y + p2.y + q2.y + a1.y) * 0.25f;
    r1.z = (z1.z + p3.x + q3.x + a1.z) * 0.25f;
    r1.w = (z1.w + p3.y + q3.y + a1.w) * 0.25f;
    acc4[o]     = r0;
    acc4[o + 1] = r1;
}

// ---------------- launch ----------------
extern "C" void kernel_launch(void* const* d_in, const int* in_sizes, int n_in,
                              void* d_out, int out_size) {
    const int*   ei   = (const int*)d_in[0];
    const int*   frm  = ei;
    const int*   to   = ei + NE;
    const float* emb  = (const float*)d_in[1];
    const float* uf   = (const float*)d_in[2];
    const float* bnf  = (const float*)d_in[3];
    const float* bgf  = (const float*)d_in[4];
    const float* Wu   = (const float*)d_in[5];
    const float* bu   = (const float*)d_in[6];
    const float* Wn   = (const float*)d_in[7];
    const float* bn   = (const float*)d_in[8];
    const float* Wg   = (const float*)d_in[9];
    const float* bg   = (const float*)d_in[10];

    float* out  = (float*)d_out;
    float* out0 = out;              // emb0 (fp32, exact)
    float* acc  = out + NN * D;     // final output, written once

    __half* hA;
    __half* hB;
    cudaGetSymbolAddress((void**)&hA, g_h16A);
    cudaGetSymbolAddress((void**)&hB, g_h16B);

    k_zero_deg<<<(NN + 255) / 256, 256>>>();
    k_emb0<<<(NN + 3) / 4, 256>>>(emb, uf, bnf, bgf, Wu, bu, Wn, bn, Wg, bg, out0);
    k_degree<<<(NE + 255) / 256, 256>>>(to);
    k_scan1<<<NBLK, SCAN_BLK>>>();
    k_scan2<<<1, 256>>>();
    k_scan3<<<NBLK, SCAN_BLK>>>();
    k_scatter<<<(NE + 255) / 256, 256>>>(frm, to);

    int prop_threads = NN * 8;
    int prop_blocks  = (prop_threads + 255) / 256;
    k_prop_mid<<<prop_blocks, 256>>>(hA, hB);                 // e1 = prop(emb0): A -> B
    k_prop_mid<<<prop_blocks, 256>>>(hB, hA);                 // e2 = prop(e1):   B -> A
    k_prop_final<<<prop_blocks, 256>>>(hA, hB,
                                       (const float4*)out0, (float4*)acc);  // e3 + combine
}

// round 6
// speedup vs baseline: 2.0572x; 1.0887x over previous
#include <cuda_runtime.h>
#include <cuda_fp16.h>
#include <stdint.h>

#define NU 100000
#define NB 50000
#define NN 150000
#define D  64
#define NE 2400000

#define SCAN_BLK 1024
#define NBLK ((NN + SCAN_BLK - 1) / SCAN_BLK)   // 147
#define NBINS 256

// ---------------- scratch (device globals: allocation-free) ----------------
__device__ __half g_h16A[NN * D];    // fp16: emb0 copy, then e2
__device__ __half g_h16B[NN * D];    // fp16: e1
__device__ int    g_deg[NN];
__device__ float  g_dinv[NN];
__device__ int    g_off[NN + 1];
__device__ int    g_cur[NN];
__device__ int2   g_csr[NE];         // (frm, norm bits) interleaved
__device__ int    g_partial[NBLK];
__device__ int    g_bins[NBINS];     // degree histogram
__device__ int    g_bin_cur[NBINS];  // placement cursors
__device__ int    g_perm[NN];        // nodes sorted by degree

// ---------------- kernels ----------------

__global__ void k_zero() {
    int i = blockIdx.x * blockDim.x + threadIdx.x;
    if (i < NN) g_deg[i] = 0;
    if (i < NBINS) g_bins[i] = 0;
}

// emb0 = embedding + concat(user_proj, book_proj); writes out0 (fp32) and fp16 copy
__global__ void k_emb0(const float* __restrict__ emb,
                       const float* __restrict__ uf,
                       const float* __restrict__ bnf,
                       const float* __restrict__ bgf,
                       const float* __restrict__ Wu, const float* __restrict__ bu,
                       const float* __restrict__ Wn, const float* __restrict__ bn,
                       const float* __restrict__ Wg, const float* __restrict__ bg,
                       float* __restrict__ out_emb0) {
    int node = blockIdx.x * 4 + (threadIdx.x >> 6);
    int d    = threadIdx.x & 63;
    if (node >= NN) return;
    float v = emb[node * D + d];
    if (node < NU) {
        const float* f = uf + node * 16;
        float s = bu[d];
#pragma unroll
        for (int k = 0; k < 16; k++) s += f[k] * Wu[k * D + d];
        v += s;
    } else {
        int b = node - NU;
        float s = bn[d] + bg[d];
        const float* fn = bnf + b * 8;
#pragma unroll
        for (int k = 0; k < 8; k++) s += fn[k] * Wn[k * D + d];
        const float* fg = bgf + b * 32;
#pragma unroll
        for (int k = 0; k < 32; k++) s += fg[k] * Wg[k * D + d];
        v += s;
    }
    int o = node * D + d;
    out_emb0[o] = v;
    g_h16A[o]   = __float2half_rn(v);
}

__global__ void k_degree(const int* __restrict__ to) {
    int e = blockIdx.x * blockDim.x + threadIdx.x;
    if (e < NE) atomicAdd(&g_deg[to[e]], 1);
}

// phase 1: per-block reduce of deg -> g_partial[b]; also dinv + degree histogram
__global__ void k_scan1() {
    __shared__ int s[SCAN_BLK / 32];
    __shared__ int hist[NBINS];
    int t = threadIdx.x;
    for (int b = t; b < NBINS; b += SCAN_BLK) hist[b] = 0;
    __syncthreads();
    int i = blockIdx.x * SCAN_BLK + t;
    int v = (i < NN) ? g_deg[i] : 0;
    if (i < NN) {
        g_dinv[i] = (v > 0) ? rsqrtf((float)v) : 0.0f;
        atomicAdd(&hist[min(v, NBINS - 1)], 1);
    }
    int w = v;
#pragma unroll
    for (int o = 16; o > 0; o >>= 1) w += __shfl_down_sync(0xffffffffu, w, o);
    if ((t & 31) == 0) s[t >> 5] = w;
    __syncthreads();
    if (t < SCAN_BLK / 32) {
        int x = s[t];
#pragma unroll
        for (int o = 16; o > 0; o >>= 1) x += __shfl_down_sync(0xffffffffu, x, o);
        if (t == 0) g_partial[blockIdx.x] = x;
    }
    __syncthreads();
    for (int b = t; b < NBINS; b += SCAN_BLK)
        if (hist[b]) atomicAdd(&g_bins[b], hist[b]);
}

// phase 2: exclusive scan of NBLK partials AND of the 256 degree bins
__global__ void k_scan2() {
    __shared__ int s[256];
    int t = threadIdx.x;
    int v = (t < NBLK) ? g_partial[t] : 0;
    s[t] = v;
    __syncthreads();
#pragma unroll
    for (int o = 1; o < 256; o <<= 1) {
        int y = (t >= o) ? s[t - o] : 0;
        __syncthreads();
        s[t] += y;
        __syncthreads();
    }
    if (t < NBLK) g_partial[t] = s[t] - v;
    __syncthreads();
    int bv = g_bins[t];
    s[t] = bv;
    __syncthreads();
#pragma unroll
    for (int o = 1; o < 256; o <<= 1) {
        int y = (t >= o) ? s[t - o] : 0;
        __syncthreads();
        s[t] += y;
        __syncthreads();
    }
    g_bin_cur[t] = s[t] - bv;   // exclusive prefix = placement start
}

// phase 3: per-block exclusive scan + block offset -> g_off, g_cur
__global__ void k_scan3() {
    __shared__ int s[SCAN_BLK];
    int t = threadIdx.x;
    int i = blockIdx.x * SCAN_BLK + t;
    int v = (i < NN) ? g_deg[i] : 0;
    s[t] = v;
    __syncthreads();
#pragma unroll
    for (int o = 1; o < SCAN_BLK; o <<= 1) {
        int y = (t >= o) ? s[t - o] : 0;
        __syncthreads();
        s[t] += y;
        __syncthreads();
    }
    if (i < NN) {
        int ex = g_partial[blockIdx.x] + s[t] - v;
        g_off[i] = ex;
        g_cur[i] = ex;
    }
    if (i == NN - 1) g_off[NN] = NE;
}

// place nodes into degree-sorted permutation
__global__ void k_place() {
    int i = blockIdx.x * blockDim.x + threadIdx.x;
    if (i < NN) {
        int b = min(g_deg[i], NBINS - 1);
        int p = atomicAdd(&g_bin_cur[b], 1);
        g_perm[p] = i;
    }
}

__global__ void k_scatter(const int* __restrict__ frm, const int* __restrict__ to) {
    int e = blockIdx.x * blockDim.x + threadIdx.x;
    if (e < NE) {
        int tt = to[e];
        int ff = frm[e];
        int p  = atomicAdd(&g_cur[tt], 1);
        float w = g_dinv[ff] * g_dinv[tt];
        g_csr[p] = make_int2(ff, __float_as_int(w));
    }
}

// gather core: 8 lanes/node, lane loads uint4 = 8 halves, fp32 accum.
// CSR chunk loads software-pipelined; inner unroll 4 (unroll 8 spilled, R4).
__device__ __forceinline__ void gather_node(const uint4* __restrict__ src16,
                                            int node, int lane,
                                            float4& a0, float4& a1) {
    int s = g_off[node];
    int e = g_off[node + 1];
    if (s >= e) return;
    int idx = s + lane;
    int2 fw = (idx < e) ? g_csr[idx] : make_int2(0, 0);
    for (int base = s; base < e; base += 8) {
        int m = min(8, e - base);
        int nidx = base + 8 + lane;
        int2 fw_next = (nidx < e) ? g_csr[nidx] : make_int2(0, 0);
#pragma unroll 4
        for (int j = 0; j < m; j++) {
            int   fj = __shfl_sync(0xffffffffu, fw.x, j, 8);
            float wj = __int_as_float(__shfl_sync(0xffffffffu, fw.y, j, 8));
            uint4 x  = src16[fj * 8 + lane];
            float2 f0 = __half22float2(*(const __half2*)&x.x);
            float2 f1 = __half22float2(*(const __half2*)&x.y);
            float2 f2 = __half22float2(*(const __half2*)&x.z);
            float2 f3 = __half22float2(*(const __half2*)&x.w);
            a0.x += wj * f0.x;  a0.y += wj * f0.y;
            a0.z += wj * f1.x;  a0.w += wj * f1.y;
            a1.x += wj * f2.x;  a1.y += wj * f2.y;
            a1.z += wj * f3.x;  a1.w += wj * f3.y;
        }
        fw = fw_next;
    }
}

// mid layer: pure gather -> fp16 store; nodes visited in degree-sorted order
__global__ void __launch_bounds__(256) k_prop_mid(const __half* __restrict__ src,
                                                  __half* __restrict__ dst) {
    int slot = (blockIdx.x * blockDim.x + threadIdx.x) >> 3;
    int lane = threadIdx.x & 7;
    if (slot >= NN) return;
    int node = g_perm[slot];
    float4 a0 = make_float4(0.f, 0.f, 0.f, 0.f);
    float4 a1 = make_float4(0.f, 0.f, 0.f, 0.f);
    gather_node((const uint4*)src, node, lane, a0, a1);
    __half2 h0 = __floats2half2_rn(a0.x, a0.y);
    __half2 h1 = __floats2half2_rn(a0.z, a0.w);
    __half2 h2 = __floats2half2_rn(a1.x, a1.y);
    __half2 h3 = __floats2half2_rn(a1.z, a1.w);
    uint4 hx;
    hx.x = *(const unsigned*)&h0;
    hx.y = *(const unsigned*)&h1;
    hx.z = *(const unsigned*)&h2;
    hx.w = *(const unsigned*)&h3;
    ((uint4*)dst)[node * 8 + lane] = hx;
}

// final layer: e3 = gather(e2); acc = (emb0 + e1 + e2 + e3) / 4, single write
__global__ void __launch_bounds__(256) k_prop_final(const __half* __restrict__ e2src,
                                                    const __half* __restrict__ e1src,
                                                    const float4* __restrict__ emb0_4,
                                                    float4* __restrict__ acc4) {
    int slot = (blockIdx.x * blockDim.x + threadIdx.x) >> 3;
    int lane = threadIdx.x & 7;
    if (slot >= NN) return;
    int node = g_perm[slot];
    float4 a0 = make_float4(0.f, 0.f, 0.f, 0.f);
    float4 a1 = make_float4(0.f, 0.f, 0.f, 0.f);
    gather_node((const uint4*)e2src, node, lane, a0, a1);   // a = e3

    int ho = node * 8 + lane;                 // uint4 index into fp16 rows
    uint4 x1 = ((const uint4*)e1src)[ho];
    uint4 x2 = ((const uint4*)e2src)[ho];
    float2 p0 = __half22float2(*(const __half2*)&x1.x);
    float2 p1 = __half22float2(*(const __half2*)&x1.y);
    float2 p2 = __half22float2(*(const __half2*)&x1.z);
    float2 p3 = __half22float2(*(const __half2*)&x1.w);
    float2 q0 = __half22float2(*(const __half2*)&x2.x);
    float2 q1 = __half22float2(*(const __half2*)&x2.y);
    float2 q2 = __half22float2(*(const __half2*)&x2.z);
    float2 q3 = __half22float2(*(const __half2*)&x2.w);

    int o = node * 16 + lane * 2;             // float4 index into fp32 rows
    float4 z0 = emb0_4[o];
    float4 z1 = emb0_4[o + 1];

    float4 r0, r1;
    r0.x = (z0.x + p0.x + q0.x + a0.x) * 0.25f;
    r0.y = (z0.y + p0.y + q0.y + a0.y) * 0.25f;
    r0.z = (z0.z + p1.x + q1.x + a0.z) * 0.25f;
    r0.w = (z0.w + p1.y + q1.y + a0.w) * 0.25f;
    r1.x = (z1.x + p2.x + q2.x + a1.x) * 0.25f;
    r1.y = (z1.y + p2.y + q2.y + a1.y) * 0.25f;
    r1.z = (z1.z + p3.x + q3.x + a1.z) * 0.25f;
    r1.w = (z1.w + p3.y + q3.y + a1.w) * 0.25f;
    acc4[o]     = r0;
    acc4[o + 1] = r1;
}

// ---------------- launch ----------------
extern "C" void kernel_launch(void* const* d_in, const int* in_sizes, int n_in,
                              void* d_out, int out_size) {
    const int*   ei   = (const int*)d_in[0];
    const int*   frm  = ei;
    const int*   to   = ei + NE;
    const float* emb  = (const float*)d_in[1];
    const float* uf   = (const float*)d_in[2];
    const float* bnf  = (const float*)d_in[3];
    const float* bgf  = (const float*)d_in[4];
    const float* Wu   = (const float*)d_in[5];
    const float* bu   = (const float*)d_in[6];
    const float* Wn   = (const float*)d_in[7];
    const float* bn   = (const float*)d_in[8];
    const float* Wg   = (const float*)d_in[9];
    const float* bg   = (const float*)d_in[10];

    float* out  = (float*)d_out;
    float* out0 = out;              // emb0 (fp32, exact)
    float* acc  = out + NN * D;     // final output, written once

    __half* hA;
    __half* hB;
    cudaGetSymbolAddress((void**)&hA, g_h16A);
    cudaGetSymbolAddress((void**)&hB, g_h16B);

    k_zero<<<(NN + 255) / 256, 256>>>();
    k_emb0<<<(NN + 3) / 4, 256>>>(emb, uf, bnf, bgf, Wu, bu, Wn, bn, Wg, bg, out0);
    k_degree<<<(NE + 255) / 256, 256>>>(to);
    k_scan1<<<NBLK, SCAN_BLK>>>();
    k_scan2<<<1, 256>>>();
    k_scan3<<<NBLK, SCAN_BLK>>>();
    k_place<<<(NN + 255) / 256, 256>>>();
    k_scatter<<<(NE + 255) / 256, 256>>>(frm, to);

    int prop_threads = NN * 8;
    int prop_blocks  = (prop_threads + 255) / 256;
    k_prop_mid<<<prop_blocks, 256>>>(hA, hB);                 // e1 = prop(emb0): A -> B
    k_prop_mid<<<prop_blocks, 256>>>(hB, hA);                 // e2 = prop(e1):   B -> A
    k_prop_final<<<prop_blocks, 256>>>(hA, hB,
                                       (const float4*)out0, (float4*)acc);  // e3 + combine
}

// round 7
// speedup vs baseline: 2.2401x; 1.0889x over previous
#include <cuda_runtime.h>
#include <cuda_fp16.h>
#include <stdint.h>

#define NU 100000
#define NB 50000
#define NN 150000
#define D  64
#define NE 2400000

#define SCAN_BLK 1024
#define NBLK ((NN + SCAN_BLK - 1) / SCAN_BLK)   // 147
#define NBINS 256

// ---------------- scratch (device globals: allocation-free) ----------------
__device__ __half g_h16A[NN * D];    // fp16: emb0 copy, then e2
__device__ __half g_h16B[NN * D];    // fp16: e1
__device__ int    g_deg[NN];
__device__ float  g_dinv[NN];
__device__ int    g_off[NN + 1];
__device__ int    g_cur[NN];
__device__ int2   g_csr[NE];         // (frm, norm bits) interleaved
__device__ int    g_partial[NBLK];
__device__ int    g_bins[NBINS];     // degree histogram
__device__ int    g_bin_cur[NBINS];  // placement cursors
__device__ int    g_perm[NN];        // nodes sorted by degree (descending)

// ---------------- kernels ----------------

__global__ void k_zero() {
    int i = blockIdx.x * blockDim.x + threadIdx.x;
    if (i < NN) g_deg[i] = 0;
    if (i < NBINS) g_bins[i] = 0;
}

// emb0 = embedding + concat(user_proj, book_proj); writes out0 (fp32) and fp16 copy
__global__ void k_emb0(const float* __restrict__ emb,
                       const float* __restrict__ uf,
                       const float* __restrict__ bnf,
                       const float* __restrict__ bgf,
                       const float* __restrict__ Wu, const float* __restrict__ bu,
                       const float* __restrict__ Wn, const float* __restrict__ bn,
                       const float* __restrict__ Wg, const float* __restrict__ bg,
                       float* __restrict__ out_emb0) {
    int node = blockIdx.x * 4 + (threadIdx.x >> 6);
    int d    = threadIdx.x & 63;
    if (node >= NN) return;
    float v = emb[node * D + d];
    if (node < NU) {
        const float* f = uf + node * 16;
        float s = bu[d];
#pragma unroll
        for (int k = 0; k < 16; k++) s += f[k] * Wu[k * D + d];
        v += s;
    } else {
        int b = node - NU;
        float s = bn[d] + bg[d];
        const float* fn = bnf + b * 8;
#pragma unroll
        for (int k = 0; k < 8; k++) s += fn[k] * Wn[k * D + d];
        const float* fg = bgf + b * 32;
#pragma unroll
        for (int k = 0; k < 32; k++) s += fg[k] * Wg[k * D + d];
        v += s;
    }
    int o = node * D + d;
    out_emb0[o] = v;
    g_h16A[o]   = __float2half_rn(v);
}

__global__ void k_degree(const int* __restrict__ to) {
    int e = blockIdx.x * blockDim.x + threadIdx.x;
    if (e < NE) atomicAdd(&g_deg[to[e]], 1);
}

// phase 1: per-block reduce of deg -> g_partial[b]; also dinv + degree histogram
__global__ void k_scan1() {
    __shared__ int s[SCAN_BLK / 32];
    __shared__ int hist[NBINS];
    int t = threadIdx.x;
    for (int b = t; b < NBINS; b += SCAN_BLK) hist[b] = 0;
    __syncthreads();
    int i = blockIdx.x * SCAN_BLK + t;
    int v = (i < NN) ? g_deg[i] : 0;
    if (i < NN) {
        g_dinv[i] = (v > 0) ? rsqrtf((float)v) : 0.0f;
        atomicAdd(&hist[min(v, NBINS - 1)], 1);
    }
    int w = v;
#pragma unroll
    for (int o = 16; o > 0; o >>= 1) w += __shfl_down_sync(0xffffffffu, w, o);
    if ((t & 31) == 0) s[t >> 5] = w;
    __syncthreads();
    if (t < SCAN_BLK / 32) {
        int x = s[t];
#pragma unroll
        for (int o = 16; o > 0; o >>= 1) x += __shfl_down_sync(0xffffffffu, x, o);
        if (t == 0) g_partial[blockIdx.x] = x;
    }
    __syncthreads();
    for (int b = t; b < NBINS; b += SCAN_BLK)
        if (hist[b]) atomicAdd(&g_bins[b], hist[b]);
}

// phase 2: exclusive scan of NBLK partials AND of the 256 degree bins
__global__ void k_scan2() {
    __shared__ int s[256];
    int t = threadIdx.x;
    int v = (t < NBLK) ? g_partial[t] : 0;
    s[t] = v;
    __syncthreads();
#pragma unroll
    for (int o = 1; o < 256; o <<= 1) {
        int y = (t >= o) ? s[t - o] : 0;
        __syncthreads();
        s[t] += y;
        __syncthreads();
    }
    if (t < NBLK) g_partial[t] = s[t] - v;
    __syncthreads();
    int bv = g_bins[t];
    s[t] = bv;
    __syncthreads();
#pragma unroll
    for (int o = 1; o < 256; o <<= 1) {
        int y = (t >= o) ? s[t - o] : 0;
        __syncthreads();
        s[t] += y;
        __syncthreads();
    }
    g_bin_cur[t] = s[t] - bv;   // exclusive prefix = placement start
}

// phase 3 (fused): per-block exclusive scan -> g_off/g_cur, AND degree-sort placement
__global__ void k_scan3_place() {
    __shared__ int s[SCAN_BLK];
    int t = threadIdx.x;
    int i = blockIdx.x * SCAN_BLK + t;
    int v = (i < NN) ? g_deg[i] : 0;
    s[t] = v;
    __syncthreads();
#pragma unroll
    for (int o = 1; o < SCAN_BLK; o <<= 1) {
        int y = (t >= o) ? s[t - o] : 0;
        __syncthreads();
        s[t] += y;
        __syncthreads();
    }
    if (i < NN) {
        int ex = g_partial[blockIdx.x] + s[t] - v;
        g_off[i] = ex;
        g_cur[i] = ex;
        // placement: descending-degree order (heavy nodes first)
        int b = min(v, NBINS - 1);
        int p = atomicAdd(&g_bin_cur[b], 1);
        g_perm[NN - 1 - p] = i;
    }
    if (i == NN - 1) g_off[NN] = NE;
}

__global__ void k_scatter(const int* __restrict__ frm, const int* __restrict__ to) {
    int e = blockIdx.x * blockDim.x + threadIdx.x;
    if (e < NE) {
        int tt = to[e];
        int ff = frm[e];
        int p  = atomicAdd(&g_cur[tt], 1);
        float w = g_dinv[ff] * g_dinv[tt];
        g_csr[p] = make_int2(ff, __float_as_int(w));
    }
}

// gather core: 8 lanes/node; CSR entry loaded directly by every lane of the
// group (same address -> L1 broadcast, replaces 2 shfls). fp32 accumulation.
__device__ __forceinline__ void gather_node(const uint4* __restrict__ src16,
                                            int node, int lane,
                                            float4& a0, float4& a1) {
    int s = g_off[node];
    int e = g_off[node + 1];
#pragma unroll 4
    for (int idx = s; idx < e; idx++) {
        int2  fw = __ldg(&g_csr[idx]);
        float wj = __int_as_float(fw.y);
        uint4 x  = src16[fw.x * 8 + lane];
        float2 f0 = __half22float2(*(const __half2*)&x.x);
        float2 f1 = __half22float2(*(const __half2*)&x.y);
        float2 f2 = __half22float2(*(const __half2*)&x.z);
        float2 f3 = __half22float2(*(const __half2*)&x.w);
        a0.x += wj * f0.x;  a0.y += wj * f0.y;
        a0.z += wj * f1.x;  a0.w += wj * f1.y;
        a1.x += wj * f2.x;  a1.y += wj * f2.y;
        a1.z += wj * f3.x;  a1.w += wj * f3.y;
    }
}

// mid layer: pure gather -> fp16 store; nodes visited in degree-sorted order
__global__ void __launch_bounds__(256) k_prop_mid(const __half* __restrict__ src,
                                                  __half* __restrict__ dst) {
    int slot = (blockIdx.x * blockDim.x + threadIdx.x) >> 3;
    int lane = threadIdx.x & 7;
    if (slot >= NN) return;
    int node = g_perm[slot];
    float4 a0 = make_float4(0.f, 0.f, 0.f, 0.f);
    float4 a1 = make_float4(0.f, 0.f, 0.f, 0.f);
    gather_node((const uint4*)src, node, lane, a0, a1);
    __half2 h0 = __floats2half2_rn(a0.x, a0.y);
    __half2 h1 = __floats2half2_rn(a0.z, a0.w);
    __half2 h2 = __floats2half2_rn(a1.x, a1.y);
    __half2 h3 = __floats2half2_rn(a1.z, a1.w);
    uint4 hx;
    hx.x = *(const unsigned*)&h0;
    hx.y = *(const unsigned*)&h1;
    hx.z = *(const unsigned*)&h2;
    hx.w = *(const unsigned*)&h3;
    ((uint4*)dst)[node * 8 + lane] = hx;
}

// final layer: e3 = gather(e2); acc = (emb0 + e1 + e2 + e3) / 4, single write
__global__ void __launch_bounds__(256) k_prop_final(const __half* __restrict__ e2src,
                                                    const __half* __restrict__ e1src,
                                                    const float4* __restrict__ emb0_4,
                                                    float4* __restrict__ acc4) {
    int slot = (blockIdx.x * blockDim.x + threadIdx.x) >> 3;
    int lane = threadIdx.x & 7;
    if (slot >= NN) return;
    int node = g_perm[slot];
    float4 a0 = make_float4(0.f, 0.f, 0.f, 0.f);
    float4 a1 = make_float4(0.f, 0.f, 0.f, 0.f);
    gather_node((const uint4*)e2src, node, lane, a0, a1);   // a = e3

    int ho = node * 8 + lane;                 // uint4 index into fp16 rows
    uint4 x1 = ((const uint4*)e1src)[ho];
    uint4 x2 = ((const uint4*)e2src)[ho];
    float2 p0 = __half22float2(*(const __half2*)&x1.x);
    float2 p1 = __half22float2(*(const __half2*)&x1.y);
    float2 p2 = __half22float2(*(const __half2*)&x1.z);
    float2 p3 = __half22float2(*(const __half2*)&x1.w);
    float2 q0 = __half22float2(*(const __half2*)&x2.x);
    float2 q1 = __half22float2(*(const __half2*)&x2.y);
    float2 q2 = __half22float2(*(const __half2*)&x2.z);
    float2 q3 = __half22float2(*(const __half2*)&x2.w);

    int o = node * 16 + lane * 2;             // float4 index into fp32 rows
    float4 z0 = emb0_4[o];
    float4 z1 = emb0_4[o + 1];

    float4 r0, r1;
    r0.x = (z0.x + p0.x + q0.x + a0.x) * 0.25f;
    r0.y = (z0.y + p0.y + q0.y + a0.y) * 0.25f;
    r0.z = (z0.z + p1.x + q1.x + a0.z) * 0.25f;
    r0.w = (z0.w + p1.y + q1.y + a0.w) * 0.25f;
    r1.x = (z1.x + p2.x + q2.x + a1.x) * 0.25f;
    r1.y = (z1.y + p2.y + q2.y + a1.y) * 0.25f;
    r1.z = (z1.z + p3.x + q3.x + a1.z) * 0.25f;
    r1.w = (z1.w + p3.y + q3.y + a1.w) * 0.25f;
    acc4[o]     = r0;
    acc4[o + 1] = r1;
}

// ---------------- launch ----------------
extern "C" void kernel_launch(void* const* d_in, const int* in_sizes, int n_in,
                              void* d_out, int out_size) {
    const int*   ei   = (const int*)d_in[0];
    const int*   frm  = ei;
    const int*   to   = ei + NE;
    const float* emb  = (const float*)d_in[1];
    const float* uf   = (const float*)d_in[2];
    const float* bnf  = (const float*)d_in[3];
    const float* bgf  = (const float*)d_in[4];
    const float* Wu   = (const float*)d_in[5];
    const float* bu   = (const float*)d_in[6];
    const float* Wn   = (const float*)d_in[7];
    const float* bn   = (const float*)d_in[8];
    const float* Wg   = (const float*)d_in[9];
    const float* bg   = (const float*)d_in[10];

    float* out  = (float*)d_out;
    float* out0 = out;              // emb0 (fp32, exact)
    float* acc  = out + NN * D;     // final output, written once

    __half* hA;
    __half* hB;
    cudaGetSymbolAddress((void**)&hA, g_h16A);
    cudaGetSymbolAddress((void**)&hB, g_h16B);

    // side stream + events for graph-parallel emb0 (host-side resources only)
    static cudaStream_t side = nullptr;
    static cudaEvent_t evFork = nullptr, evJoin = nullptr;
    if (!side) {
        cudaStreamCreateWithFlags(&side, cudaStreamNonBlocking);
        cudaEventCreateWithFlags(&evFork, cudaEventDisableTiming);
        cudaEventCreateWithFlags(&evJoin, cudaEventDisableTiming);
    }

    // fork: emb0 runs concurrently with the edge-processing chain
    cudaEventRecord(evFork, 0);
    cudaStreamWaitEvent(side, evFork, 0);
    k_emb0<<<(NN + 3) / 4, 256, 0, side>>>(emb, uf, bnf, bgf,
                                           Wu, bu, Wn, bn, Wg, bg, out0);
    cudaEventRecord(evJoin, side);

    // edge chain on the main stream
    k_zero<<<(NN + 255) / 256, 256>>>();
    k_degree<<<(NE + 255) / 256, 256>>>(to);
    k_scan1<<<NBLK, SCAN_BLK>>>();
    k_scan2<<<1, 256>>>();
    k_scan3_place<<<NBLK, SCAN_BLK>>>();
    k_scatter<<<(NE + 255) / 256, 256>>>(frm, to);

    // join: props need both emb0 (side) and CSR (main)
    cudaStreamWaitEvent(0, evJoin, 0);

    int prop_threads = NN * 8;
    int prop_blocks  = (prop_threads + 255) / 256;
    k_prop_mid<<<prop_blocks, 256>>>(hA, hB);                 // e1 = prop(emb0): A -> B
    k_prop_mid<<<prop_blocks, 256>>>(hB, hA);                 // e2 = prop(e1):   B -> A
    k_prop_final<<<prop_blocks, 256>>>(hA, hB,
                                       (const float4*)out0, (float4*)acc);  // e3 + combine
}